// round 3
// baseline (speedup 1.0000x reference)
#include <cuda_runtime.h>
#include <math.h>
#include <stdint.h>

#define FULLMASK 0xFFFFFFFFu

static const int MAXN = 250000;
static const int MAXE = 4000000;
static const int NG   = 512;

// ---------------- constant weight bank ----------------
#define O_NW1 0
#define O_NB1 64
#define O_NW2 80
#define O_NB2 336
#define O_NW3 352
#define O_NB3 608
#define O_EW1 624
#define O_EB1 752
#define O_EW2 768
#define O_EB2 1024
#define O_EW3 1040
#define O_EB3 1296
#define O_WL  1312
#define O_BL  1568
#define O_WR  1584
#define O_BR  1840
#define O_WE  1856
#define O_ATT 2112
#define O_GATB 2128
#define O_OW1 2144
#define O_OB1 2400
#define O_GAMMA 2416
#define O_BETA 2432
#define O_OW2 2448
#define O_OB2 2464
#define CW_TOTAL 2465

__constant__ float c_w[CW_TOTAL];

// ---------------- device scratch ----------------
__device__ __align__(16) float g_xl[MAXN * 16];
__device__ __align__(16) float g_xr[MAXN * 16];
__device__ __align__(16) float g_s[MAXE];
__device__ __align__(16) float g_sloop[MAXN];
__device__ __align__(16) unsigned g_menc[MAXN];
__device__ __align__(16) float g_den[MAXN];
__device__ __align__(16) float g_acc[MAXN * 16];
__device__ __align__(16) float g_esum[16];
__device__ __align__(16) float g_emw[16];
__device__ __align__(16) unsigned g_pool[NG * 16];
__device__ __align__(16) int g_src[MAXE];
__device__ __align__(16) int g_dst[MAXE];
__device__ __align__(16) int g_batch32[MAXN];
__device__ int g_is64;

// ---------------- helpers ----------------
__device__ __forceinline__ unsigned fenc(float f) {
    unsigned u = __float_as_uint(f);
    return (u & 0x80000000u) ? ~u : (u | 0x80000000u);
}
__device__ __forceinline__ float fdec(unsigned u) {
    return __uint_as_float((u & 0x80000000u) ? (u & 0x7FFFFFFFu) : ~u);
}
#define ENC_NEG_INF 0x007FFFFFu  // fenc(-inf)

__device__ __forceinline__ void ld16(const float* __restrict__ p, float* v) {
    const float4* q = (const float4*)p;
#pragma unroll
    for (int k = 0; k < 4; k++) {
        float4 t = q[k];
        v[4 * k + 0] = t.x; v[4 * k + 1] = t.y;
        v[4 * k + 2] = t.z; v[4 * k + 3] = t.w;
    }
}
__device__ __forceinline__ void st16(float* __restrict__ p, const float* v) {
    float4* q = (float4*)p;
#pragma unroll
    for (int k = 0; k < 4; k++) {
        float4 t;
        t.x = v[4 * k + 0]; t.y = v[4 * k + 1];
        t.z = v[4 * k + 2]; t.w = v[4 * k + 3];
        q[k] = t;
    }
}

// ---------------- dtype detection + index conversion ----------------
// If edge_index is int64 (nonneg < 2^31), odd 32-bit words are all 0.
__global__ void k_detect(const unsigned* __restrict__ eraw) {
    if (threadIdx.x == 0) {
        int is64 = 1;
        for (int i = 0; i < 32; i++)
            if (eraw[2 * i + 1] != 0u) { is64 = 0; break; }
        g_is64 = is64;
    }
}

__global__ void k_convert(const void* __restrict__ eraw,
                          const void* __restrict__ braw, int N, int E) {
    int i = blockIdx.x * blockDim.x + threadIdx.x;
    int is64 = g_is64;
    if (i < E) {
        if (is64) {
            g_src[i] = (int)((const long long*)eraw)[i];
            g_dst[i] = (int)((const long long*)eraw)[E + i];
        } else {
            g_src[i] = ((const int*)eraw)[i];
            g_dst[i] = ((const int*)eraw)[E + i];
        }
    }
    if (i < N) {
        g_batch32[i] = is64 ? (int)((const long long*)braw)[i]
                            : ((const int*)braw)[i];
    }
}

// ---------------- kernels ----------------
__global__ void k_init(int N) {
    int i = blockIdx.x * blockDim.x + threadIdx.x;
    if (i < N * 16) g_acc[i] = 0.f;
    if (i < N) { g_menc[i] = ENC_NEG_INF; g_den[i] = 0.f; }
    if (i < NG * 16) g_pool[i] = ENC_NEG_INF;
    if (i < 16) g_esum[i] = 0.f;
}

// node MLP -> h -> xl, xr
__global__ void k_node(const float* __restrict__ x, int N) {
    int i = blockIdx.x * blockDim.x + threadIdx.x;
    if (i >= N) return;
    float4 xv = ((const float4*)x)[i];
    float xin[4] = {xv.x, xv.y, xv.z, xv.w};
    float a[16], b[16], h[16];
#pragma unroll
    for (int j = 0; j < 16; j++) {
        float t = c_w[O_NB1 + j];
#pragma unroll
        for (int q = 0; q < 4; q++) t += xin[q] * c_w[O_NW1 + q * 16 + j];
        a[j] = fmaxf(t, 0.f);
    }
#pragma unroll
    for (int j = 0; j < 16; j++) {
        float t = c_w[O_NB2 + j];
#pragma unroll
        for (int q = 0; q < 16; q++) t += a[q] * c_w[O_NW2 + q * 16 + j];
        b[j] = fmaxf(t, 0.f);
    }
#pragma unroll
    for (int j = 0; j < 16; j++) {
        float t = c_w[O_NB3 + j];
#pragma unroll
        for (int q = 0; q < 16; q++) t += b[q] * c_w[O_NW3 + q * 16 + j];
        h[j] = t;
    }
    float xl[16], xr[16];
#pragma unroll
    for (int j = 0; j < 16; j++) {
        float tl = c_w[O_BL + j], tr = c_w[O_BR + j];
#pragma unroll
        for (int q = 0; q < 16; q++) {
            tl += h[q] * c_w[O_WL + q * 16 + j];
            tr += h[q] * c_w[O_WR + q * 16 + j];
        }
        xl[j] = tl; xr[j] = tr;
    }
    st16(&g_xl[i * 16], xl);
    st16(&g_xr[i * 16], xr);
}

// edge MLP, attention score s, segment max over dst, accumulate e-sum
__global__ void k_edge1(const float* __restrict__ ea, int E) {
    int tid = threadIdx.x;
    __shared__ float ss[16];
    if (tid < 16) ss[tid] = 0.f;
    __syncthreads();

    float lsum[16];
#pragma unroll
    for (int j = 0; j < 16; j++) lsum[j] = 0.f;

    for (int e = blockIdx.x * blockDim.x + tid; e < E; e += gridDim.x * blockDim.x) {
        float4 e0 = ((const float4*)ea)[e * 2];
        float4 e1 = ((const float4*)ea)[e * 2 + 1];
        float in[8] = {e0.x, e0.y, e0.z, e0.w, e1.x, e1.y, e1.z, e1.w};
        float a[16], b[16], ev[16];
#pragma unroll
        for (int j = 0; j < 16; j++) {
            float t = c_w[O_EB1 + j];
#pragma unroll
            for (int q = 0; q < 8; q++) t += in[q] * c_w[O_EW1 + q * 16 + j];
            a[j] = fmaxf(t, 0.f);
        }
#pragma unroll
        for (int j = 0; j < 16; j++) {
            float t = c_w[O_EB2 + j];
#pragma unroll
            for (int q = 0; q < 16; q++) t += a[q] * c_w[O_EW2 + q * 16 + j];
            b[j] = fmaxf(t, 0.f);
        }
#pragma unroll
        for (int j = 0; j < 16; j++) {
            float t = c_w[O_EB3 + j];
#pragma unroll
            for (int q = 0; q < 16; q++) t += b[q] * c_w[O_EW3 + q * 16 + j];
            ev[j] = t;
            lsum[j] += t;
        }
        int src = g_src[e];
        int dst = g_dst[e];
        float xls[16], xrd[16];
        ld16(&g_xl[src * 16], xls);
        ld16(&g_xr[dst * 16], xrd);
        float s = 0.f;
#pragma unroll
        for (int j = 0; j < 16; j++) {
            float u = xls[j] + xrd[j];
#pragma unroll
            for (int q = 0; q < 16; q++) u += ev[q] * c_w[O_WE + q * 16 + j];
            u = (u > 0.f) ? u : 0.2f * u;
            s += u * c_w[O_ATT + j];
        }
        g_s[e] = s;
        atomicMax(&g_menc[dst], fenc(s));
    }

#pragma unroll
    for (int j = 0; j < 16; j++) {
        float v = lsum[j];
#pragma unroll
        for (int off = 16; off > 0; off >>= 1)
            v += __shfl_xor_sync(FULLMASK, v, off);
        if ((tid & 31) == 0) atomicAdd(&ss[j], v);
    }
    __syncthreads();
    if (tid < 16) atomicAdd(&g_esum[tid], ss[tid]);
}

// emean @ we
__global__ void k_emw(int E) {
    int j = threadIdx.x;
    if (j >= 16) return;
    float invE = 1.f / (float)E;
    float s = 0.f;
#pragma unroll
    for (int q = 0; q < 16; q++) s += (g_esum[q] * invE) * c_w[O_WE + q * 16 + j];
    g_emw[j] = s;
}

// self-loop attention score, fold into segment max
__global__ void k_selfloop(int N) {
    int i = blockIdx.x * blockDim.x + threadIdx.x;
    if (i >= N) return;
    float xls[16], xrd[16];
    ld16(&g_xl[i * 16], xls);
    ld16(&g_xr[i * 16], xrd);
    float s = 0.f;
#pragma unroll
    for (int j = 0; j < 16; j++) {
        float u = xls[j] + xrd[j] + g_emw[j];
        u = (u > 0.f) ? u : 0.2f * u;
        s += u * c_w[O_ATT + j];
    }
    g_sloop[i] = s;
    atomicMax(&g_menc[i], fenc(s));
}

// exp-weights, weighted scatter-sum of xl[src]
__global__ void k_edge2(int E) {
    int e = blockIdx.x * blockDim.x + threadIdx.x;
    if (e >= E) return;
    int src = g_src[e];
    int dst = g_dst[e];
    float m = fdec(g_menc[dst]);
    float w = __expf(g_s[e] - m);
    atomicAdd(&g_den[dst], w);
    float xls[16];
    ld16(&g_xl[src * 16], xls);
#pragma unroll
    for (int k = 0; k < 16; k++)
        atomicAdd(&g_acc[dst * 16 + k], w * xls[k]);
}

// finalize node output, pool max per graph
__global__ void k_final(int N) {
    int i = blockIdx.x * blockDim.x + threadIdx.x;
    bool valid = (i < N);
    int g = -2;
    float vals[16];
    if (valid) {
        float m = fdec(g_menc[i]);
        float wl = __expf(g_sloop[i] - m);
        float den = g_den[i] + wl;
        float inv = 1.f / den;
        float xls[16];
        ld16(&g_xl[i * 16], xls);
#pragma unroll
        for (int k = 0; k < 16; k++)
            vals[k] = (g_acc[i * 16 + k] + wl * xls[k]) * inv + c_w[O_GATB + k];
        g = g_batch32[i];
    } else {
#pragma unroll
        for (int k = 0; k < 16; k++) vals[k] = -INFINITY;
    }
    int lane = threadIdx.x & 31;
    int g0 = __shfl_sync(FULLMASK, g, 0);
    bool uni = __all_sync(FULLMASK, g == g0);
    if (uni && g0 >= 0) {
#pragma unroll
        for (int k = 0; k < 16; k++) {
            float v = vals[k];
#pragma unroll
            for (int off = 16; off > 0; off >>= 1)
                v = fmaxf(v, __shfl_xor_sync(FULLMASK, v, off));
            if (lane == 0) atomicMax(&g_pool[g0 * 16 + k], fenc(v));
        }
    } else if (valid) {
#pragma unroll
        for (int k = 0; k < 16; k++)
            atomicMax(&g_pool[g * 16 + k], fenc(vals[k]));
    }
}

// output MLP with batchnorm over 512 graphs
__global__ void k_head(float* __restrict__ out, int out_size) {
    int g = threadIdx.x;
    __shared__ float ssum[16], ssq[16];
    if (g < 16) { ssum[g] = 0.f; ssq[g] = 0.f; }
    __syncthreads();
    float p[16];
#pragma unroll
    for (int k = 0; k < 16; k++) p[k] = fdec(g_pool[g * 16 + k]);
    float z[16];
#pragma unroll
    for (int j = 0; j < 16; j++) {
        float t = c_w[O_OB1 + j];
#pragma unroll
        for (int q = 0; q < 16; q++) t += p[q] * c_w[O_OW1 + q * 16 + j];
        z[j] = t;
    }
#pragma unroll
    for (int j = 0; j < 16; j++) {
        atomicAdd(&ssum[j], z[j]);
        atomicAdd(&ssq[j], z[j] * z[j]);
    }
    __syncthreads();
    float h = c_w[O_OB2];
    const float invG = 1.f / (float)NG;
#pragma unroll
    for (int j = 0; j < 16; j++) {
        float mu = ssum[j] * invG;
        float var = ssq[j] * invG - mu * mu;
        float zn = (z[j] - mu) * rsqrtf(var + 1e-5f) * c_w[O_GAMMA + j] + c_w[O_BETA + j];
        zn = (zn > 0.f) ? zn : 0.01f * zn;
        h += zn * c_w[O_OW2 + j];
    }
    out[g] = h;
    if (out_size >= 2 * NG) out[NG + g] = 1.f / (1.f + expf(-h));
}

// ---------------- launch ----------------
extern "C" void kernel_launch(void* const* d_in, const int* in_sizes, int n_in,
                              void* d_out, int out_size) {
    // --- bind the 4 big tensors by unique element counts ---
    int ix = -1, iei = -1, ib = -1, iea = -1;
    for (int i = 0; i < n_in; i++) {
        int s = in_sizes[i];
        if (s == 250000 * 4)       ix = i;   // x [N,4]
        else if (s == 2 * 4000000) iei = i;  // edge_index [2,E]
        else if (s == 250000)      ib = i;   // batch [N]
        else if (s == 4000000 * 8) iea = i;  // edge_attr [E,8]
    }
    const float* x = (const float*)d_in[ix];
    const void* eraw = d_in[iei];
    const void* braw = d_in[ib];
    const float* ea = (const float*)d_in[iea];
    const int N = 250000;
    const int E = 4000000;

    // --- weights: match expected size pattern in order ---
    static const int sz[25] = {64, 16, 256, 16, 256, 16,
                               128, 16, 256, 16, 256, 16,
                               256, 16, 256, 16, 256, 16, 16,
                               256, 16, 16, 16, 16, 1};
    size_t off = 0;
    int k = 0;
    for (int i = 0; i < n_in && k < 25; i++) {
        if (i == ix || i == iei || i == ib || i == iea) continue;
        if (in_sizes[i] != sz[k]) continue;
        cudaMemcpyToSymbolAsync(c_w, d_in[i], sz[k] * sizeof(float), off,
                                cudaMemcpyDeviceToDevice, 0);
        off += sz[k] * sizeof(float);
        k++;
    }

    const int B = 256;
    k_detect<<<1, 32>>>((const unsigned*)eraw);
    k_convert<<<(E + B - 1) / B, B>>>(eraw, braw, N, E);
    k_init<<<(N * 16 + B - 1) / B, B>>>(N);
    k_node<<<(N + B - 1) / B, B>>>(x, N);
    k_edge1<<<4096, B>>>(ea, E);
    k_emw<<<1, 16>>>(E);
    k_selfloop<<<(N + B - 1) / B, B>>>(N);
    k_edge2<<<(E + B - 1) / B, B>>>(E);
    k_final<<<(N + B - 1) / B, B>>>(N);
    k_head<<<1, 512>>>((float*)d_out, out_size);
}

// round 4
// speedup vs baseline: 1.6048x; 1.6048x over previous
#include <cuda_runtime.h>
#include <math.h>
#include <stdint.h>

#define FULLMASK 0xFFFFFFFFu

static const int MAXN = 250000;
static const int MAXE = 4000000;
static const int NG   = 512;

// ---------------- constant weight bank ----------------
#define O_NW1 0
#define O_NB1 64
#define O_NW2 80
#define O_NB2 336
#define O_NW3 352
#define O_NB3 608
#define O_EW1 624
#define O_EB1 752
#define O_EW2 768
#define O_EB2 1024
#define O_EW3 1040
#define O_EB3 1296
#define O_WL  1312
#define O_BL  1568
#define O_WR  1584
#define O_BR  1840
#define O_WE  1856
#define O_ATT 2112
#define O_GATB 2128
#define O_OW1 2144
#define O_OB1 2400
#define O_GAMMA 2416
#define O_BETA 2432
#define O_OW2 2448
#define O_OB2 2464
#define CW_TOTAL 2465

__constant__ float c_w[CW_TOTAL];

// ---------------- device scratch ----------------
__device__ __align__(16) float g_xl[MAXN * 16];
__device__ __align__(16) float g_xr[MAXN * 16];
__device__ __align__(16) float g_den[MAXN];
__device__ __align__(16) float g_acc[MAXN * 16];
__device__ __align__(16) float g_evwsum[16];
__device__ __align__(16) float g_emw[16];
__device__ __align__(16) unsigned g_pool[NG * 16];
__device__ __align__(16) int g_src[MAXE];
__device__ __align__(16) int g_dst[MAXE];
__device__ __align__(16) int g_batch32[MAXN];
__device__ __align__(16) float g_wp[256];  // ew3 @ we
__device__ __align__(16) float g_cp[16];   // eb3 @ we
__device__ int g_is64;

// ---------------- helpers ----------------
__device__ __forceinline__ unsigned fenc(float f) {
    unsigned u = __float_as_uint(f);
    return (u & 0x80000000u) ? ~u : (u | 0x80000000u);
}
__device__ __forceinline__ float fdec(unsigned u) {
    return __uint_as_float((u & 0x80000000u) ? (u & 0x7FFFFFFFu) : ~u);
}
#define ENC_NEG_INF 0x007FFFFFu  // fenc(-inf)

__device__ __forceinline__ void ld16(const float* __restrict__ p, float* v) {
    const float4* q = (const float4*)p;
#pragma unroll
    for (int k = 0; k < 4; k++) {
        float4 t = q[k];
        v[4 * k + 0] = t.x; v[4 * k + 1] = t.y;
        v[4 * k + 2] = t.z; v[4 * k + 3] = t.w;
    }
}
__device__ __forceinline__ void st16(float* __restrict__ p, const float* v) {
    float4* q = (float4*)p;
#pragma unroll
    for (int k = 0; k < 4; k++) {
        float4 t;
        t.x = v[4 * k + 0]; t.y = v[4 * k + 1];
        t.z = v[4 * k + 2]; t.w = v[4 * k + 3];
        q[k] = t;
    }
}

// ---- packed f32x2 ops (Blackwell) ----
typedef unsigned long long u64;
__device__ __forceinline__ u64 pk2(float lo, float hi) {
    u64 d;
    asm("mov.b64 %0, {%1, %2};" : "=l"(d)
        : "r"(__float_as_uint(lo)), "r"(__float_as_uint(hi)));
    return d;
}
__device__ __forceinline__ void upk2(u64 v, float& lo, float& hi) {
    unsigned a, b;
    asm("mov.b64 {%0, %1}, %2;" : "=r"(a), "=r"(b) : "l"(v));
    lo = __uint_as_float(a); hi = __uint_as_float(b);
}
__device__ __forceinline__ u64 fma2(u64 a, u64 b, u64 c) {
    u64 d;
    asm("fma.rn.f32x2 %0, %1, %2, %3;" : "=l"(d) : "l"(a), "l"(b), "l"(c));
    return d;
}
__device__ __forceinline__ u64 dup2(float x) { return pk2(x, x); }

// 2-edge MLP layer: out = (relu?) (in @ W + b), W: [NQ,16] row-major in shared
template <int NQ>
__device__ __forceinline__ void layer2x(const float* a0, const float* a1,
                                        const float* __restrict__ w,
                                        const float* __restrict__ b,
                                        float* o0, float* o1, bool relu) {
    u64 A0[8], A1[8];
    const u64* bp = (const u64*)b;
#pragma unroll
    for (int jp = 0; jp < 8; jp++) { u64 bb = bp[jp]; A0[jp] = bb; A1[jp] = bb; }
#pragma unroll
    for (int q = 0; q < NQ; q++) {
        u64 d0 = dup2(a0[q]), d1 = dup2(a1[q]);
        const u64* wq = (const u64*)(w + q * 16);
#pragma unroll
        for (int jp = 0; jp < 8; jp++) {
            u64 wv = wq[jp];
            A0[jp] = fma2(d0, wv, A0[jp]);
            A1[jp] = fma2(d1, wv, A1[jp]);
        }
    }
#pragma unroll
    for (int jp = 0; jp < 8; jp++) {
        float x, y;
        upk2(A0[jp], x, y);
        if (relu) { x = fmaxf(x, 0.f); y = fmaxf(y, 0.f); }
        o0[2 * jp] = x; o0[2 * jp + 1] = y;
        upk2(A1[jp], x, y);
        if (relu) { x = fmaxf(x, 0.f); y = fmaxf(y, 0.f); }
        o1[2 * jp] = x; o1[2 * jp + 1] = y;
    }
}

__device__ __forceinline__ void red_f32(float* p, float v) {
    asm volatile("red.global.add.f32 [%0], %1;" :: "l"(p), "f"(v) : "memory");
}
__device__ __forceinline__ void red_v4(float* p, float a, float b, float c, float d) {
    asm volatile("red.global.add.v4.f32 [%0], {%1, %2, %3, %4};"
                 :: "l"(p), "f"(a), "f"(b), "f"(c), "f"(d) : "memory");
}

// ---------------- dtype detection + index conversion ----------------
__global__ void k_detect(const unsigned* __restrict__ eraw) {
    if (threadIdx.x == 0) {
        int is64 = 1;
        for (int i = 0; i < 32; i++)
            if (eraw[2 * i + 1] != 0u) { is64 = 0; break; }
        g_is64 = is64;
    }
}

__global__ void k_convert(const void* __restrict__ eraw,
                          const void* __restrict__ braw, int N, int E) {
    int i = blockIdx.x * blockDim.x + threadIdx.x;
    int is64 = g_is64;
    if (i < E) {
        if (is64) {
            g_src[i] = (int)((const long long*)eraw)[i];
            g_dst[i] = (int)((const long long*)eraw)[E + i];
        } else {
            g_src[i] = ((const int*)eraw)[i];
            g_dst[i] = ((const int*)eraw)[E + i];
        }
    }
    if (i < N) {
        g_batch32[i] = is64 ? (int)((const long long*)braw)[i]
                            : ((const int*)braw)[i];
    }
}

// ---------------- init + weight folding ----------------
__global__ void k_init(int N) {
    int i = blockIdx.x * blockDim.x + threadIdx.x;
    if (i < N * 16) g_acc[i] = 0.f;
    if (i < N) g_den[i] = 0.f;
    if (i < NG * 16) g_pool[i] = ENC_NEG_INF;
    if (i < 16) g_evwsum[i] = 0.f;
}

__global__ void k_fold() {
    int t = threadIdx.x;  // 256 threads
    int q = t >> 4, j = t & 15;
    float s = 0.f;
#pragma unroll
    for (int k = 0; k < 16; k++)
        s += c_w[O_EW3 + q * 16 + k] * c_w[O_WE + k * 16 + j];
    g_wp[q * 16 + j] = s;
    if (t < 16) {
        float c = 0.f;
#pragma unroll
        for (int k = 0; k < 16; k++)
            c += c_w[O_EB3 + k] * c_w[O_WE + k * 16 + t];
        g_cp[t] = c;
    }
}

// ---------------- node MLP -> h -> xl, xr ----------------
__global__ void k_node(const float* __restrict__ x, int N) {
    int i = blockIdx.x * blockDim.x + threadIdx.x;
    if (i >= N) return;
    float4 xv = ((const float4*)x)[i];
    float xin[4] = {xv.x, xv.y, xv.z, xv.w};
    float a[16], b[16], h[16];
#pragma unroll
    for (int j = 0; j < 16; j++) {
        float t = c_w[O_NB1 + j];
#pragma unroll
        for (int q = 0; q < 4; q++) t += xin[q] * c_w[O_NW1 + q * 16 + j];
        a[j] = fmaxf(t, 0.f);
    }
#pragma unroll
    for (int j = 0; j < 16; j++) {
        float t = c_w[O_NB2 + j];
#pragma unroll
        for (int q = 0; q < 16; q++) t += a[q] * c_w[O_NW2 + q * 16 + j];
        b[j] = fmaxf(t, 0.f);
    }
#pragma unroll
    for (int j = 0; j < 16; j++) {
        float t = c_w[O_NB3 + j];
#pragma unroll
        for (int q = 0; q < 16; q++) t += b[q] * c_w[O_NW3 + q * 16 + j];
        h[j] = t;
    }
    float xl[16], xr[16];
#pragma unroll
    for (int j = 0; j < 16; j++) {
        float tl = c_w[O_BL + j], tr = c_w[O_BR + j];
#pragma unroll
        for (int q = 0; q < 16; q++) {
            tl += h[q] * c_w[O_WL + q * 16 + j];
            tr += h[q] * c_w[O_WR + q * 16 + j];
        }
        xl[j] = tl; xr[j] = tr;
    }
    st16(&g_xl[i * 16], xl);
    st16(&g_xr[i * 16], xr);
}

// ---------------- fused edge pass ----------------
// edge MLP (with we folded into layer3) -> score -> w = exp(s)
// -> red den[dst], red v4 acc[dst] ; accumulate sum(ev@we) for the e-mean term
__global__ void __launch_bounds__(256) k_edge(const float* __restrict__ ea, int E) {
    __shared__ __align__(8) float sw1[128], sw2[256], sw3[256];
    __shared__ __align__(8) float sb1[16], sb2[16], sb3[16], satt[16];
    __shared__ float sred[16];
    int tid = threadIdx.x;
    for (int i = tid; i < 128; i += 256) sw1[i] = c_w[O_EW1 + i];
    for (int i = tid; i < 256; i += 256) { sw2[i] = c_w[O_EW2 + i]; sw3[i] = g_wp[i]; }
    if (tid < 16) {
        sb1[tid] = c_w[O_EB1 + tid];
        sb2[tid] = c_w[O_EB2 + tid];
        sb3[tid] = g_cp[tid];
        satt[tid] = c_w[O_ATT + tid];
        sred[tid] = 0.f;
    }
    __syncthreads();

    float lsum[16];
#pragma unroll
    for (int j = 0; j < 16; j++) lsum[j] = 0.f;

    int e0 = (blockIdx.x * 256 + tid) * 2;
    if (e0 < E) {
        int e1 = e0 + 1;
        bool has1 = (e1 < E);
        int e1v = has1 ? e1 : e0;

        float4 p0 = ((const float4*)ea)[e0 * 2];
        float4 p1 = ((const float4*)ea)[e0 * 2 + 1];
        float4 q0 = ((const float4*)ea)[e1v * 2];
        float4 q1 = ((const float4*)ea)[e1v * 2 + 1];
        float in0[8] = {p0.x, p0.y, p0.z, p0.w, p1.x, p1.y, p1.z, p1.w};
        float in1[8] = {q0.x, q0.y, q0.z, q0.w, q1.x, q1.y, q1.z, q1.w};

        float a0[16], a1[16], b0[16], b1[16], ev0[16], ev1[16];
        layer2x<8>(in0, in1, sw1, sb1, a0, a1, true);
        layer2x<16>(a0, a1, sw2, sb2, b0, b1, true);
        layer2x<16>(b0, b1, sw3, sb3, ev0, ev1, false);  // = ev @ we + eb3 @ we

#pragma unroll
        for (int j = 0; j < 16; j++) {
            lsum[j] += ev0[j];
            if (has1) lsum[j] += ev1[j];
        }

        // edge 0
        {
            int src = g_src[e0], dst = g_dst[e0];
            float xls[16], xrd[16];
            ld16(&g_xl[src * 16], xls);
            ld16(&g_xr[dst * 16], xrd);
            float s = 0.f;
#pragma unroll
            for (int j = 0; j < 16; j++) {
                float u = xls[j] + xrd[j] + ev0[j];
                u = (u > 0.f) ? u : 0.2f * u;
                s += u * satt[j];
            }
            float w = __expf(s);
            red_f32(&g_den[dst], w);
            float* ap = &g_acc[dst * 16];
#pragma unroll
            for (int k = 0; k < 4; k++)
                red_v4(ap + 4 * k, w * xls[4 * k], w * xls[4 * k + 1],
                       w * xls[4 * k + 2], w * xls[4 * k + 3]);
        }
        // edge 1
        if (has1) {
            int src = g_src[e1], dst = g_dst[e1];
            float xls[16], xrd[16];
            ld16(&g_xl[src * 16], xls);
            ld16(&g_xr[dst * 16], xrd);
            float s = 0.f;
#pragma unroll
            for (int j = 0; j < 16; j++) {
                float u = xls[j] + xrd[j] + ev1[j];
                u = (u > 0.f) ? u : 0.2f * u;
                s += u * satt[j];
            }
            float w = __expf(s);
            red_f32(&g_den[dst], w);
            float* ap = &g_acc[dst * 16];
#pragma unroll
            for (int k = 0; k < 4; k++)
                red_v4(ap + 4 * k, w * xls[4 * k], w * xls[4 * k + 1],
                       w * xls[4 * k + 2], w * xls[4 * k + 3]);
        }
    }

    // block reduce lsum -> g_evwsum
#pragma unroll
    for (int j = 0; j < 16; j++) {
        float v = lsum[j];
#pragma unroll
        for (int off = 16; off > 0; off >>= 1)
            v += __shfl_xor_sync(FULLMASK, v, off);
        if ((tid & 31) == 0) atomicAdd(&sred[j], v);
    }
    __syncthreads();
    if (tid < 16) red_f32(&g_evwsum[tid], sred[tid]);
}

// mean(ev @ we)
__global__ void k_emw(int E) {
    int j = threadIdx.x;
    if (j < 16) g_emw[j] = g_evwsum[j] / (float)E;
}

// finalize: self-loop term, normalize, bias, pool max per graph
__global__ void k_final(int N) {
    int i = blockIdx.x * blockDim.x + threadIdx.x;
    bool valid = (i < N);
    int g = -2;
    float vals[16];
    if (valid) {
        float xls[16], xrd[16];
        ld16(&g_xl[i * 16], xls);
        ld16(&g_xr[i * 16], xrd);
        float s = 0.f;
#pragma unroll
        for (int j = 0; j < 16; j++) {
            float u = xls[j] + xrd[j] + g_emw[j];
            u = (u > 0.f) ? u : 0.2f * u;
            s += u * c_w[O_ATT + j];
        }
        float wl = __expf(s);
        float inv = 1.f / (g_den[i] + wl);
#pragma unroll
        for (int k = 0; k < 16; k++)
            vals[k] = (g_acc[i * 16 + k] + wl * xls[k]) * inv + c_w[O_GATB + k];
        g = g_batch32[i];
    } else {
#pragma unroll
        for (int k = 0; k < 16; k++) vals[k] = -INFINITY;
    }
    int lane = threadIdx.x & 31;
    int g0 = __shfl_sync(FULLMASK, g, 0);
    bool uni = __all_sync(FULLMASK, g == g0);
    if (uni && g0 >= 0) {
#pragma unroll
        for (int k = 0; k < 16; k++) {
            float v = vals[k];
#pragma unroll
            for (int off = 16; off > 0; off >>= 1)
                v = fmaxf(v, __shfl_xor_sync(FULLMASK, v, off));
            if (lane == 0) atomicMax(&g_pool[g0 * 16 + k], fenc(v));
        }
    } else if (valid) {
#pragma unroll
        for (int k = 0; k < 16; k++)
            atomicMax(&g_pool[g * 16 + k], fenc(vals[k]));
    }
}

// output MLP with batchnorm over 512 graphs
__global__ void k_head(float* __restrict__ out, int out_size) {
    int g = threadIdx.x;
    __shared__ float ssum[16], ssq[16];
    if (g < 16) { ssum[g] = 0.f; ssq[g] = 0.f; }
    __syncthreads();
    float p[16];
#pragma unroll
    for (int k = 0; k < 16; k++) p[k] = fdec(g_pool[g * 16 + k]);
    float z[16];
#pragma unroll
    for (int j = 0; j < 16; j++) {
        float t = c_w[O_OB1 + j];
#pragma unroll
        for (int q = 0; q < 16; q++) t += p[q] * c_w[O_OW1 + q * 16 + j];
        z[j] = t;
    }
#pragma unroll
    for (int j = 0; j < 16; j++) {
        atomicAdd(&ssum[j], z[j]);
        atomicAdd(&ssq[j], z[j] * z[j]);
    }
    __syncthreads();
    float h = c_w[O_OB2];
    const float invG = 1.f / (float)NG;
#pragma unroll
    for (int j = 0; j < 16; j++) {
        float mu = ssum[j] * invG;
        float var = ssq[j] * invG - mu * mu;
        float zn = (z[j] - mu) * rsqrtf(var + 1e-5f) * c_w[O_GAMMA + j] + c_w[O_BETA + j];
        zn = (zn > 0.f) ? zn : 0.01f * zn;
        h += zn * c_w[O_OW2 + j];
    }
    out[g] = h;
    if (out_size >= 2 * NG) out[NG + g] = 1.f / (1.f + expf(-h));
}

// ---------------- launch ----------------
extern "C" void kernel_launch(void* const* d_in, const int* in_sizes, int n_in,
                              void* d_out, int out_size) {
    int ix = -1, iei = -1, ib = -1, iea = -1;
    for (int i = 0; i < n_in; i++) {
        int s = in_sizes[i];
        if (s == 250000 * 4)       ix = i;   // x [N,4]
        else if (s == 2 * 4000000) iei = i;  // edge_index [2,E]
        else if (s == 250000)      ib = i;   // batch [N]
        else if (s == 4000000 * 8) iea = i;  // edge_attr [E,8]
    }
    const float* x = (const float*)d_in[ix];
    const void* eraw = d_in[iei];
    const void* braw = d_in[ib];
    const float* ea = (const float*)d_in[iea];
    const int N = 250000;
    const int E = 4000000;

    static const int sz[25] = {64, 16, 256, 16, 256, 16,
                               128, 16, 256, 16, 256, 16,
                               256, 16, 256, 16, 256, 16, 16,
                               256, 16, 16, 16, 16, 1};
    size_t off = 0;
    int k = 0;
    for (int i = 0; i < n_in && k < 25; i++) {
        if (i == ix || i == iei || i == ib || i == iea) continue;
        if (in_sizes[i] != sz[k]) continue;
        cudaMemcpyToSymbolAsync(c_w, d_in[i], sz[k] * sizeof(float), off,
                                cudaMemcpyDeviceToDevice, 0);
        off += sz[k] * sizeof(float);
        k++;
    }

    const int B = 256;
    k_detect<<<1, 32>>>((const unsigned*)eraw);
    k_convert<<<(E + B - 1) / B, B>>>(eraw, braw, N, E);
    k_init<<<(N * 16 + B - 1) / B, B>>>(N);
    k_fold<<<1, 256>>>();
    k_node<<<(N + B - 1) / B, B>>>(x, N);
    k_edge<<<(E / 2 + B - 1) / B, B>>>(ea, E);
    k_emw<<<1, 16>>>(E);
    k_final<<<(N + B - 1) / B, B>>>(N);
    k_head<<<1, 512>>>((float*)d_out, out_size);
}